// round 8
// baseline (speedup 1.0000x reference)
#include <cuda_runtime.h>
#include <cuda_fp16.h>

// Shape fixed by reference setup: N=16, C=3, H=512, W=512, patch=15.
#define N_       16
#define H_       512
#define W_       512
#define PLANE    (H_ * W_)
#define STRIPS   8
#define STRIP_H  64
#define TPB      1024
#define NBLK     (N_ * STRIPS)      // 128
#define ITERS    10                 // 8-row groups covering h0-8 .. h0+71
#define RSLOT    32                 // ring slots (power of 2)
#define SD_STRIDE 532               // 8 pad + 512 + 12 pad
#define S4_STRIDE 132               // 2 pad + 128 + 2 pad
// Ring: [RSLOT][W_] of uint2 {half2(l,u), half2(v,pad)} = 128 KB
#define RING_U2   (RSLOT * W_)
#define SMEM_BYTES (RING_U2 * 8 + 24 * SD_STRIDE * 4 + 24 * S4_STRIDE * 4)

typedef unsigned long long u64;

__device__ double g_accum[3];
__device__ int    g_done = 0;

// ---- packed f32x2 helpers (Blackwell FFMA2/FMUL2 via PTX) ----
__device__ __forceinline__ u64 pk(float lo, float hi) {
    u64 r; asm("mov.b64 %0, {%1,%2};" : "=l"(r) : "f"(lo), "f"(hi)); return r;
}
__device__ __forceinline__ void upk(float& lo, float& hi, u64 v) {
    asm("mov.b64 {%0,%1}, %2;" : "=f"(lo), "=f"(hi) : "l"(v));
}
__device__ __forceinline__ u64 fma2(u64 a, u64 b, u64 c) {
    u64 d; asm("fma.rn.f32x2 %0, %1, %2, %3;" : "=l"(d) : "l"(a), "l"(b), "l"(c));
    return d;
}
__device__ __forceinline__ u64 mul2(u64 a, u64 b) {
    u64 d; asm("mul.rn.f32x2 %0, %1, %2;" : "=l"(d) : "l"(a), "l"(b));
    return d;
}

__device__ __forceinline__ float f_func(float t) {
    // reference: cbrt(t) if t > 0.008856 else 7.787*t + 16/116
    float cb = __powf(t, 1.0f / 3.0f);     // MUFU.LG2 + FMUL + MUFU.EX2
    return (t > 0.008856f) ? cb : fmaf(7.787f, t, 16.0f / 116.0f);
}

__device__ __forceinline__ unsigned pack2h(float a, float b) {
    __half2 h = __floats2half2_rn(a, b);
    return *(unsigned*)&h;
}
__device__ __forceinline__ float lo2f(unsigned w) { return __low2float(*(__half2*)&w); }
__device__ __forceinline__ float hi2f(unsigned w) { return __high2float(*(__half2*)&w); }

// Fully fused, 8-rows-per-iteration (TPB=1024, ty=0..7):
//  A: clamped vectorized loads + luv-diff (packed 2 px/instr) -> per-ty sd/s4
//  B: horizontal 15-box via block-sum + increments -> fp16 ring (2x STS.128)
//  C: vertical 15-box running sum per column (threads < 512) + square + acc;
//     olds read directly (32-slot ring -> no slot collision with this group).
__global__ void __launch_bounds__(TPB, 1) fused_kernel(
    const float* __restrict__ in, const float* __restrict__ tgt,
    float* __restrict__ out) {
    extern __shared__ char smraw[];
    uint2* ring = (uint2*)smraw;                         // [RSLOT][W_]
    float* sd   = (float*)(smraw + RING_U2 * 8);         // [8][3][SD_STRIDE]
    float* s4   = sd + 24 * SD_STRIDE;                   // [8][3][S4_STRIDE]

    const int t  = threadIdx.x;
    const int tx = t & 127;
    const int ty = t >> 7;                               // 0..7
    const int n     = blockIdx.x >> 3;
    const int strip = blockIdx.x & 7;
    const int h0    = strip * STRIP_H;                   // h0 % 64 == 0

    // Packed constants (XYZ scales folded into matrix rows 0 and 2).
    #define PC(v) pk((v), (v))
    const u64 K00 = PC(0.4124564f / 0.95047f), K01 = PC(0.3575761f / 0.95047f),
              K02 = PC(0.1804375f / 0.95047f);
    const u64 K10 = PC(0.2126729f), K11 = PC(0.7151522f), K12 = PC(0.0721750f);
    const u64 K20 = PC(0.0193339f / 1.08883f), K21 = PC(0.1191920f / 1.08883f),
              K22 = PC(0.9503041f / 1.08883f);
    const u64 C116 = PC(116.0f), CM16 = PC(-16.0f), C13 = PC(13.0f),
              NEG1 = PC(-1.0f);
    #undef PC

    auto luv2 = [&](u64 r, u64 g, u64 b, u64& L, u64& U, u64& V) {
        u64 x = fma2(r, K00, fma2(g, K01, mul2(b, K02)));
        u64 y = fma2(r, K10, fma2(g, K11, mul2(b, K12)));
        u64 z = fma2(r, K20, fma2(g, K21, mul2(b, K22)));
        float x0, x1, y0, y1, z0, z1;
        upk(x0, x1, x); upk(y0, y1, y); upk(z0, z1, z);
        u64 fx = pk(f_func(x0), f_func(x1));
        u64 fy = pk(f_func(y0), f_func(y1));
        u64 fz = pk(f_func(z0), f_func(z1));
        L = fma2(fy, C116, CM16);
        u64 t13 = mul2(L, C13);
        U = mul2(t13, fma2(fy, NEG1, fx));
        V = mul2(t13, fma2(fz, NEG1, fy));
    };

    // Init: zero ring; zero sd/s4 pads (stay zero forever).
    for (int i = t; i < RING_U2; i += TPB) ring[i] = make_uint2(0u, 0u);
    if (t < 480) {                         // 24 planes x 20 pad slots
        int p = t / 20, k = t % 20;
        int j = (k < 8) ? k : (512 + k);   // 0..7 or 520..531
        sd[p * SD_STRIDE + j] = 0.f;
    }
    if (t < 96) {                          // 24 planes x 4 pad slots
        int p = t / 4, k = t % 4;
        int j = (k < 2) ? k : (128 + k);   // 0,1 or 130,131
        s4[p * S4_STRIDE + j] = 0.f;
    }
    __syncthreads();

    const float4* inA = (const float4*)in;
    const float4* inB = (const float4*)tgt;
    const int P4    = PLANE / 4;                 // 65536
    const int base4 = n * 3 * P4 + tx;
    const int h0m7  = h0 - 7;

    float* sdt = sd + ty * 3 * SD_STRIDE;        // this thread's row buffers
    float* s4t = s4 + ty * 3 * S4_STRIDE;

    float vs0 = 0.f, vs1 = 0.f, vs2 = 0.f;
    float ac0 = 0.f, ac1 = 0.f, ac2 = 0.f;

    #pragma unroll 4
    for (int it = 0; it < ITERS; ++it) {
        const int grel = 8 * it - 8;             // group base row rel. to h0
        const int hr   = h0 + grel + ty;         // this thread's input row

        // ---- phase A: unconditional clamped loads (issue first) ----
        const bool valid = ((unsigned)(hr - h0m7) <= 77u) &&
                           ((unsigned)hr < (unsigned)H_);
        const int hrc = min(max(hr, 0), H_ - 1);
        const int rb  = base4 + hrc * (W_ / 4);
        float4 ra = inA[rb], ga = inA[rb + P4], ba = inA[rb + 2 * P4];
        float4 rc = inB[rb], gc = inB[rb + P4], bc = inB[rb + 2 * P4];

        // ---- luv diff, packed 2 px/instr ----
        u64 d0a = 0, d1a = 0, d2a = 0, d0b = 0, d1b = 0, d2b = 0;
        if (valid) {
            u64 lA, uA, vA, lB, uB, vB;
            luv2(pk(ra.x, ra.y), pk(ga.x, ga.y), pk(ba.x, ba.y), lA, uA, vA);
            luv2(pk(rc.x, rc.y), pk(gc.x, gc.y), pk(bc.x, bc.y), lB, uB, vB);
            d0a = fma2(lB, NEG1, lA);
            d1a = fma2(uB, NEG1, uA);
            d2a = fma2(vB, NEG1, vA);
            luv2(pk(ra.z, ra.w), pk(ga.z, ga.w), pk(ba.z, ba.w), lA, uA, vA);
            luv2(pk(rc.z, rc.w), pk(gc.z, gc.w), pk(bc.z, bc.w), lB, uB, vB);
            d0b = fma2(lB, NEG1, lA);
            d1b = fma2(uB, NEG1, uA);
            d2b = fma2(vB, NEG1, vA);
        }
        {
            float4 s;
            upk(s.x, s.y, d0a); upk(s.z, s.w, d0b);
            *(float4*)&sdt[8 + 4 * tx] = s;
            s4t[2 + tx] = (s.x + s.y) + (s.z + s.w);
            upk(s.x, s.y, d1a); upk(s.z, s.w, d1b);
            *(float4*)&sdt[SD_STRIDE + 8 + 4 * tx] = s;
            s4t[S4_STRIDE + 2 + tx] = (s.x + s.y) + (s.z + s.w);
            upk(s.x, s.y, d2a); upk(s.z, s.w, d2b);
            *(float4*)&sdt[2 * SD_STRIDE + 8 + 4 * tx] = s;
            s4t[2 * S4_STRIDE + 2 + tx] = (s.x + s.y) + (s.z + s.w);
        }
        __syncthreads();

        // ---- phase B: 15-tap hbox for row grel+ty, pixels 4tx..4tx+3 ----
        {
            float hbL[4], hbU[4], hbV[4];
            #pragma unroll
            for (int ch = 0; ch < 3; ch++) {
                const float* sdc = sdt + ch * SD_STRIDE;
                const float* s4c = s4t + ch * S4_STRIDE;
                float s0 = s4c[tx] + s4c[tx + 1] + s4c[tx + 2] + s4c[tx + 3];
                float4 dL = *(const float4*)&sdc[4 * tx];        // d[4tx-8..4tx-5]
                float4 dR = *(const float4*)&sdc[16 + 4 * tx];   // d[4tx+8..4tx+11]
                float* hb = (ch == 0) ? hbL : (ch == 1) ? hbU : hbV;
                hb[0] = s0 - dL.x;
                hb[1] = hb[0] + dR.x - dL.y;
                hb[2] = hb[1] + dR.y - dL.z;
                hb[3] = hb[2] + dR.z - dL.w;
            }
            uint4* wp = (uint4*)(ring + ((grel + ty) & 31) * W_ + 4 * tx);
            uint4 w0, w1;
            w0.x = pack2h(hbL[0], hbU[0]); w0.y = pack2h(hbV[0], 0.f);
            w0.z = pack2h(hbL[1], hbU[1]); w0.w = pack2h(hbV[1], 0.f);
            w1.x = pack2h(hbL[2], hbU[2]); w1.y = pack2h(hbV[2], 0.f);
            w1.z = pack2h(hbL[3], hbU[3]); w1.w = pack2h(hbV[3], 0.f);
            wp[0] = w0;
            wp[1] = w1;
        }
        __syncthreads();

        // ---- phase C: vertical running sum for column t (t < 512) ----
        if (t < W_) {
            #pragma unroll
            for (int j = 0; j < 8; j++) {
                const int r = grel + j;
                uint2 nw = ring[((r & 31) << 9) + t];        // row r
                uint2 ow = ring[(((r + 17) & 31) << 9) + t]; // row r-15
                vs0 += lo2f(nw.x) - lo2f(ow.x);
                vs1 += hi2f(nw.x) - hi2f(ow.x);
                vs2 += lo2f(nw.y) - lo2f(ow.y);
                if (r >= 7 && r <= 70) {     // output row r-7 in strip
                    ac0 = fmaf(vs0, vs0, ac0);
                    ac1 = fmaf(vs1, vs1, ac1);
                    ac2 = fmaf(vs2, vs2, ac2);
                }
            }
        }
    }

    // ---- block reduction (upper half contributes zeros) ----
    #pragma unroll
    for (int o = 16; o > 0; o >>= 1) {
        ac0 += __shfl_down_sync(0xffffffffu, ac0, o);
        ac1 += __shfl_down_sync(0xffffffffu, ac1, o);
        ac2 += __shfl_down_sync(0xffffffffu, ac2, o);
    }
    __syncthreads();
    float* red = sd;                               // reuse smem
    int wid = t >> 5, lane = t & 31;
    if (lane == 0) { red[wid] = ac0; red[32 + wid] = ac1; red[64 + wid] = ac2; }
    __syncthreads();
    if (t < 3) {
        float s = 0.f;
        #pragma unroll
        for (int i = 0; i < 32; i++) s += red[t * 32 + i];
        atomicAdd(&g_accum[t], (double)s);
    }
    __threadfence();
    __syncthreads();

    // Last block finalizes and resets global state (graph-replay safe).
    __shared__ int is_last;
    if (t == 0) is_last = (atomicAdd(&g_done, 1) == NBLK - 1);
    __syncthreads();
    if (is_last && t == 0) {
        double total = g_accum[0] + g_accum[1] + g_accum[2];
        out[0] = (float)(total / (double)((size_t)N_ * PLANE));
        g_accum[0] = 0.0; g_accum[1] = 0.0; g_accum[2] = 0.0;
        g_done = 0;
    }
}

extern "C" void kernel_launch(void* const* d_in, const int* in_sizes, int n_in,
                              void* d_out, int out_size) {
    const float* in  = (const float*)d_in[0];
    const float* tgt = (const float*)d_in[1];
    float* out = (float*)d_out;

    cudaFuncSetAttribute(fused_kernel,
                         cudaFuncAttributeMaxDynamicSharedMemorySize, SMEM_BYTES);
    fused_kernel<<<NBLK, TPB, SMEM_BYTES>>>(in, tgt, out);
}

// round 9
// speedup vs baseline: 1.4830x; 1.4830x over previous
#include <cuda_runtime.h>
#include <cuda_fp16.h>

// Shape fixed by reference setup: N=16, C=3, H=512, W=512, patch=15.
#define N_       16
#define H_       512
#define W_       512
#define PLANE    (H_ * W_)
#define TPB      512
#define NBLK     296                // = 148 SMs x 2 blocks, perfectly balanced
#define ITERS    11                 // 4-row groups; covers sh<=29 (grel -8..32)
#define RSLOT    16                 // ring slots (power of 2)
#define SD_STRIDE 532               // 8 pad + 512 + 12 pad
#define S4_STRIDE 132               // 2 pad + 128 + 2 pad
// Ring: [RSLOT][W_] of uint2 {half2(l,u), half2(v,pad)} = 64 KB
#define RING_U2   (RSLOT * W_)
#define SMEM_BYTES (RING_U2 * 8 + 12 * SD_STRIDE * 4 + 12 * S4_STRIDE * 4)

typedef unsigned long long u64;

__device__ double g_accum[3];
__device__ int    g_done = 0;

// ---- packed f32x2 helpers (Blackwell FFMA2/FMUL2 via PTX) ----
__device__ __forceinline__ u64 pk(float lo, float hi) {
    u64 r; asm("mov.b64 %0, {%1,%2};" : "=l"(r) : "f"(lo), "f"(hi)); return r;
}
__device__ __forceinline__ void upk(float& lo, float& hi, u64 v) {
    asm("mov.b64 {%0,%1}, %2;" : "=f"(lo), "=f"(hi) : "l"(v));
}
__device__ __forceinline__ u64 fma2(u64 a, u64 b, u64 c) {
    u64 d; asm("fma.rn.f32x2 %0, %1, %2, %3;" : "=l"(d) : "l"(a), "l"(b), "l"(c));
    return d;
}
__device__ __forceinline__ u64 mul2(u64 a, u64 b) {
    u64 d; asm("mul.rn.f32x2 %0, %1, %2;" : "=l"(d) : "l"(a), "l"(b));
    return d;
}

__device__ __forceinline__ float f_func(float t) {
    // reference: cbrt(t) if t > 0.008856 else 7.787*t + 16/116
    float cb = __powf(t, 1.0f / 3.0f);     // MUFU.LG2 + FMUL + MUFU.EX2
    return (t > 0.008856f) ? cb : fmaf(7.787f, t, 16.0f / 116.0f);
}

__device__ __forceinline__ unsigned pack2h(float a, float b) {
    __half2 h = __floats2half2_rn(a, b);
    return *(unsigned*)&h;
}
__device__ __forceinline__ float lo2f(unsigned w) { return __low2float(*(__half2*)&w); }
__device__ __forceinline__ float hi2f(unsigned w) { return __high2float(*(__half2*)&w); }

// Fully fused, 4-rows-per-iteration, packed-f32x2 luv math, balanced grid:
//  A: clamped vectorized loads + ring-old reads + luv-diff (2 px/instr)
//  B: horizontal 15-box via block-sum + increments -> ring (2x STS.128)
//  C: vertical 15-box running sum per column + square + accumulate
__global__ void __launch_bounds__(TPB, 2) fused_kernel(
    const float* __restrict__ in, const float* __restrict__ tgt,
    float* __restrict__ out) {
    extern __shared__ char smraw[];
    uint2* ring = (uint2*)smraw;                         // [RSLOT][W_]
    float* sd   = (float*)(smraw + RING_U2 * 8);         // [4][3][SD_STRIDE]
    float* s4   = sd + 12 * SD_STRIDE;                   // [4][3][S4_STRIDE]

    const int t  = threadIdx.x;
    const int tx = t & 127;
    const int ty = t >> 7;

    // Balanced decomposition: images 0..7 -> 19 strips, images 8..15 -> 18.
    int n, s, S;
    {
        int blk = blockIdx.x;
        if (blk < 152) { n = blk / 19; s = blk - n * 19; S = 19; }
        else { int b = blk - 152; int q = b / 18; n = 8 + q; s = b - q * 18; S = 18; }
    }
    const int h0 = (H_ * s) / S;
    const int sh = (H_ * (s + 1)) / S - h0;              // 26..29

    // Packed constants (XYZ scales folded into matrix rows 0 and 2).
    #define PC(v) pk((v), (v))
    const u64 K00 = PC(0.4124564f / 0.95047f), K01 = PC(0.3575761f / 0.95047f),
              K02 = PC(0.1804375f / 0.95047f);
    const u64 K10 = PC(0.2126729f), K11 = PC(0.7151522f), K12 = PC(0.0721750f);
    const u64 K20 = PC(0.0193339f / 1.08883f), K21 = PC(0.1191920f / 1.08883f),
              K22 = PC(0.9503041f / 1.08883f);
    const u64 C116 = PC(116.0f), CM16 = PC(-16.0f), C13 = PC(13.0f),
              NEG1 = PC(-1.0f);
    #undef PC

    auto luv2 = [&](u64 r, u64 g, u64 b, u64& L, u64& U, u64& V) {
        u64 x = fma2(r, K00, fma2(g, K01, mul2(b, K02)));
        u64 y = fma2(r, K10, fma2(g, K11, mul2(b, K12)));
        u64 z = fma2(r, K20, fma2(g, K21, mul2(b, K22)));
        float x0, x1, y0, y1, z0, z1;
        upk(x0, x1, x); upk(y0, y1, y); upk(z0, z1, z);
        u64 fx = pk(f_func(x0), f_func(x1));
        u64 fy = pk(f_func(y0), f_func(y1));
        u64 fz = pk(f_func(z0), f_func(z1));
        L = fma2(fy, C116, CM16);
        u64 t13 = mul2(L, C13);
        U = mul2(t13, fma2(fy, NEG1, fx));
        V = mul2(t13, fma2(fz, NEG1, fy));
    };

    // Init: zero ring; zero sd/s4 pads (stay zero forever).
    for (int i = t; i < RING_U2; i += TPB) ring[i] = make_uint2(0u, 0u);
    if (t < 240) {
        int p = t / 20, k = t % 20;
        int j = (k < 8) ? k : (512 + k);          // 0..7 or 520..531
        sd[p * SD_STRIDE + j] = 0.f;
    }
    if (t < 48) {
        int p = t / 4, k = t % 4;
        int j = (k < 2) ? k : (128 + k);          // 0,1 or 130,131
        s4[p * S4_STRIDE + j] = 0.f;
    }
    __syncthreads();

    const float4* inA = (const float4*)in;
    const float4* inB = (const float4*)tgt;
    const int P4    = PLANE / 4;                 // 65536
    const int base4 = n * 3 * P4 + tx;
    const int h0m7  = h0 - 7;
    const unsigned vspan = (unsigned)(sh + 13);  // rows h0-7 .. h0+sh+6

    float* sdt = sd + ty * 3 * SD_STRIDE;        // this thread's row buffers
    float* s4t = s4 + ty * 3 * S4_STRIDE;

    float vs0 = 0.f, vs1 = 0.f, vs2 = 0.f;
    float ac0 = 0.f, ac1 = 0.f, ac2 = 0.f;

    #pragma unroll 4
    for (int it = 0; it < ITERS; ++it) {
        const int grel = 4 * it - 8;             // group base row rel. to h0
        const int hr   = h0 + grel + ty;         // this thread's input row

        // ---- phase A: unconditional clamped loads (issue first) ----
        const bool valid = ((unsigned)(hr - h0m7) <= vspan) &&
                           ((unsigned)hr < (unsigned)H_);
        const int hrc = min(max(hr, 0), H_ - 1);
        const int rb  = base4 + hrc * (W_ / 4);
        float4 ra = inA[rb], ga = inA[rb + P4], ba = inA[rb + 2 * P4];
        float4 rc = inB[rb], gc = inB[rb + P4], bc = inB[rb + 2 * P4];

        // Ring olds (consumed in phase C; must be read before phase B writes).
        uint2 old[4];
        #pragma unroll
        for (int j = 0; j < 4; j++)
            old[j] = ring[((grel + 1 + j) & 15) * W_ + t];

        // ---- luv diff, packed 2 px/instr ----
        u64 d0a = 0, d1a = 0, d2a = 0, d0b = 0, d1b = 0, d2b = 0;
        if (valid) {
            u64 lA, uA, vA, lB, uB, vB;
            luv2(pk(ra.x, ra.y), pk(ga.x, ga.y), pk(ba.x, ba.y), lA, uA, vA);
            luv2(pk(rc.x, rc.y), pk(gc.x, gc.y), pk(bc.x, bc.y), lB, uB, vB);
            d0a = fma2(lB, NEG1, lA);
            d1a = fma2(uB, NEG1, uA);
            d2a = fma2(vB, NEG1, vA);
            luv2(pk(ra.z, ra.w), pk(ga.z, ga.w), pk(ba.z, ba.w), lA, uA, vA);
            luv2(pk(rc.z, rc.w), pk(gc.z, gc.w), pk(bc.z, bc.w), lB, uB, vB);
            d0b = fma2(lB, NEG1, lA);
            d1b = fma2(uB, NEG1, uA);
            d2b = fma2(vB, NEG1, vA);
        }
        {
            float4 sv;
            upk(sv.x, sv.y, d0a); upk(sv.z, sv.w, d0b);
            *(float4*)&sdt[8 + 4 * tx] = sv;
            s4t[2 + tx] = (sv.x + sv.y) + (sv.z + sv.w);
            upk(sv.x, sv.y, d1a); upk(sv.z, sv.w, d1b);
            *(float4*)&sdt[SD_STRIDE + 8 + 4 * tx] = sv;
            s4t[S4_STRIDE + 2 + tx] = (sv.x + sv.y) + (sv.z + sv.w);
            upk(sv.x, sv.y, d2a); upk(sv.z, sv.w, d2b);
            *(float4*)&sdt[2 * SD_STRIDE + 8 + 4 * tx] = sv;
            s4t[2 * S4_STRIDE + 2 + tx] = (sv.x + sv.y) + (sv.z + sv.w);
        }
        __syncthreads();

        // ---- phase B: 15-tap hbox for row grel+ty, pixels 4tx..4tx+3 ----
        {
            float hbL[4], hbU[4], hbV[4];
            #pragma unroll
            for (int ch = 0; ch < 3; ch++) {
                const float* sdc = sdt + ch * SD_STRIDE;
                const float* s4c = s4t + ch * S4_STRIDE;
                float s0 = s4c[tx] + s4c[tx + 1] + s4c[tx + 2] + s4c[tx + 3];
                float4 dL = *(const float4*)&sdc[4 * tx];        // d[4tx-8..4tx-5]
                float4 dR = *(const float4*)&sdc[16 + 4 * tx];   // d[4tx+8..4tx+11]
                float* hb = (ch == 0) ? hbL : (ch == 1) ? hbU : hbV;
                hb[0] = s0 - dL.x;
                hb[1] = hb[0] + dR.x - dL.y;
                hb[2] = hb[1] + dR.y - dL.z;
                hb[3] = hb[2] + dR.z - dL.w;
            }
            uint4* wp = (uint4*)(ring + ((grel + ty) & 15) * W_ + 4 * tx);
            uint4 w0, w1;
            w0.x = pack2h(hbL[0], hbU[0]); w0.y = pack2h(hbV[0], 0.f);
            w0.z = pack2h(hbL[1], hbU[1]); w0.w = pack2h(hbV[1], 0.f);
            w1.x = pack2h(hbL[2], hbU[2]); w1.y = pack2h(hbV[2], 0.f);
            w1.z = pack2h(hbL[3], hbU[3]); w1.w = pack2h(hbV[3], 0.f);
            wp[0] = w0;
            wp[1] = w1;
        }
        __syncthreads();

        // ---- phase C: vertical running sum for column t, 4 new rows ----
        #pragma unroll
        for (int j = 0; j < 4; j++) {
            const int r = grel + j;
            uint2 nw = ring[((r & 15) << 9) + t];
            vs0 += lo2f(nw.x) - lo2f(old[j].x);
            vs1 += hi2f(nw.x) - hi2f(old[j].x);
            vs2 += lo2f(nw.y) - lo2f(old[j].y);
            if ((unsigned)(r - 7) < (unsigned)sh) {   // output row r-7 in strip
                ac0 = fmaf(vs0, vs0, ac0);
                ac1 = fmaf(vs1, vs1, ac1);
                ac2 = fmaf(vs2, vs2, ac2);
            }
        }
    }

    // ---- block reduction ----
    #pragma unroll
    for (int o = 16; o > 0; o >>= 1) {
        ac0 += __shfl_down_sync(0xffffffffu, ac0, o);
        ac1 += __shfl_down_sync(0xffffffffu, ac1, o);
        ac2 += __shfl_down_sync(0xffffffffu, ac2, o);
    }
    __syncthreads();
    float* red = sd;                               // reuse smem
    int wid = t >> 5, lane = t & 31;
    if (lane == 0) { red[wid] = ac0; red[16 + wid] = ac1; red[32 + wid] = ac2; }
    __syncthreads();
    if (t < 3) {
        float sm = 0.f;
        #pragma unroll
        for (int i = 0; i < 16; i++) sm += red[t * 16 + i];
        atomicAdd(&g_accum[t], (double)sm);
    }
    __threadfence();
    __syncthreads();

    // Last block finalizes and resets global state (graph-replay safe).
    __shared__ int is_last;
    if (t == 0) is_last = (atomicAdd(&g_done, 1) == NBLK - 1);
    __syncthreads();
    if (is_last && t == 0) {
        double total = g_accum[0] + g_accum[1] + g_accum[2];
        out[0] = (float)(total / (double)((size_t)N_ * PLANE));
        g_accum[0] = 0.0; g_accum[1] = 0.0; g_accum[2] = 0.0;
        g_done = 0;
    }
}

extern "C" void kernel_launch(void* const* d_in, const int* in_sizes, int n_in,
                              void* d_out, int out_size) {
    const float* in  = (const float*)d_in[0];
    const float* tgt = (const float*)d_in[1];
    float* out = (float*)d_out;

    cudaFuncSetAttribute(fused_kernel,
                         cudaFuncAttributeMaxDynamicSharedMemorySize, SMEM_BYTES);
    fused_kernel<<<NBLK, TPB, SMEM_BYTES>>>(in, tgt, out);
}

// round 10
// speedup vs baseline: 1.5703x; 1.0588x over previous
#include <cuda_runtime.h>
#include <cuda_fp16.h>

// Shape fixed by reference setup: N=16, C=3, H=512, W=512, patch=15.
#define N_       16
#define H_       512
#define W_       512
#define PLANE    (H_ * W_)
#define TPB      512
#define NBLK     296                // = 148 SMs x 2 blocks, balanced
#define ITERS    11                 // 4-row groups; covers sh<=29
#define RSLOT    24
#define SD_STRIDE 532               // halves: 8 pad + 512 + 12 pad
#define S4_STRIDE 132               // floats: 2 pad + 128 + 2 pad

// smem layout (bytes):
//   ring_lu : [24][512] uint (half2{l,u})          = 49152
//   ring_v  : [24][512] half                       = 24576
//   sd      : [2][4][3][SD_STRIDE] half (dbl-buf)  = 25536
//   s4      : [2][4][3][S4_STRIDE] float (dbl-buf) = 12672
#define OFF_RV   49152
#define OFF_SD   73728
#define OFF_S4   99264
#define SMEM_BYTES 111936

typedef unsigned long long u64;

__device__ double g_accum[3];
__device__ int    g_done = 0;

// ---- packed f32x2 helpers (Blackwell FFMA2/FMUL2 via PTX) ----
__device__ __forceinline__ u64 pk(float lo, float hi) {
    u64 r; asm("mov.b64 %0, {%1,%2};" : "=l"(r) : "f"(lo), "f"(hi)); return r;
}
__device__ __forceinline__ void upk(float& lo, float& hi, u64 v) {
    asm("mov.b64 {%0,%1}, %2;" : "=f"(lo), "=f"(hi) : "l"(v));
}
__device__ __forceinline__ u64 fma2(u64 a, u64 b, u64 c) {
    u64 d; asm("fma.rn.f32x2 %0, %1, %2, %3;" : "=l"(d) : "l"(a), "l"(b), "l"(c));
    return d;
}
__device__ __forceinline__ u64 mul2(u64 a, u64 b) {
    u64 d; asm("mul.rn.f32x2 %0, %1, %2;" : "=l"(d) : "l"(a), "l"(b));
    return d;
}

__device__ __forceinline__ float f_func(float t) {
    // reference: cbrt(t) if t > 0.008856 else 7.787*t + 16/116
    float cb = __powf(t, 1.0f / 3.0f);     // MUFU.LG2 + FMUL + MUFU.EX2
    return (t > 0.008856f) ? cb : fmaf(7.787f, t, 16.0f / 116.0f);
}

__device__ __forceinline__ unsigned pack2h(float a, float b) {
    __half2 h = __floats2half2_rn(a, b);
    return *(unsigned*)&h;
}
__device__ __forceinline__ float h2f(__half h) { return __half2float(h); }

// Fully fused, 4-rows-per-group, ONE barrier per group:
//   A(g): loads + packed luv-diff -> fp16 sd (buffer it&1) + fp32 s4
//   bar
//   B(g): 15-tap hbox -> split fp16 ring (slot disjointness vs C)
//   C(g-1): vertical running sum from ring (deferred one group)
__global__ void __launch_bounds__(TPB, 2) fused_kernel(
    const float* __restrict__ in, const float* __restrict__ tgt,
    float* __restrict__ out) {
    extern __shared__ char smraw[];
    unsigned* ring_lu = (unsigned*)smraw;                // [24][512]
    __half*   ring_vh = (__half*)(smraw + OFF_RV);       // [24][512]
    __half*   sdh     = (__half*)(smraw + OFF_SD);       // [2][4][3][532]
    float*    s4f     = (float*)(smraw + OFF_S4);        // [2][4][3][132]

    const int t  = threadIdx.x;
    const int tx = t & 127;
    const int ty = t >> 7;

    // Balanced decomposition: images 0..7 -> 19 strips, images 8..15 -> 18.
    int n, s, S;
    {
        int blk = blockIdx.x;
        if (blk < 152) { n = blk / 19; s = blk - n * 19; S = 19; }
        else { int b = blk - 152; int q = b / 18; n = 8 + q; s = b - q * 18; S = 18; }
    }
    const int h0 = (H_ * s) / S;
    const int sh = (H_ * (s + 1)) / S - h0;              // 26..29

    // Packed constants (XYZ scales folded into matrix rows 0 and 2).
    #define PC(v) pk((v), (v))
    const u64 K00 = PC(0.4124564f / 0.95047f), K01 = PC(0.3575761f / 0.95047f),
              K02 = PC(0.1804375f / 0.95047f);
    const u64 K10 = PC(0.2126729f), K11 = PC(0.7151522f), K12 = PC(0.0721750f);
    const u64 K20 = PC(0.0193339f / 1.08883f), K21 = PC(0.1191920f / 1.08883f),
              K22 = PC(0.9503041f / 1.08883f);
    const u64 C116 = PC(116.0f), CM16 = PC(-16.0f), C13 = PC(13.0f),
              NEG1 = PC(-1.0f);
    #undef PC

    auto luv2 = [&](u64 r, u64 g, u64 b, u64& L, u64& U, u64& V) {
        u64 x = fma2(r, K00, fma2(g, K01, mul2(b, K02)));
        u64 y = fma2(r, K10, fma2(g, K11, mul2(b, K12)));
        u64 z = fma2(r, K20, fma2(g, K21, mul2(b, K22)));
        float x0, x1, y0, y1, z0, z1;
        upk(x0, x1, x); upk(y0, y1, y); upk(z0, z1, z);
        u64 fx = pk(f_func(x0), f_func(x1));
        u64 fy = pk(f_func(y0), f_func(y1));
        u64 fz = pk(f_func(z0), f_func(z1));
        L = fma2(fy, C116, CM16);
        u64 t13 = mul2(L, C13);
        U = mul2(t13, fma2(fy, NEG1, fx));
        V = mul2(t13, fma2(fz, NEG1, fy));
    };

    // Init: zero ring (both arrays); zero sd/s4 pads (both buffers).
    for (int i = t; i < RSLOT * W_; i += TPB) {
        ring_lu[i] = 0u;
        ring_vh[i] = __float2half(0.f);
    }
    if (t < 480) {                           // 24 sd planes x 20 pad slots
        int p = t / 20, k = t % 20;
        int j = (k < 8) ? k : (512 + k);     // 0..7 or 520..531
        sdh[p * SD_STRIDE + j] = __float2half(0.f);
    }
    if (t < 96) {                            // 24 s4 planes x 4 pad slots
        int p = t / 4, k = t % 4;
        int j = (k < 2) ? k : (128 + k);     // 0,1 or 130,131
        s4f[p * S4_STRIDE + j] = 0.f;
    }
    __syncthreads();

    const float4* inA = (const float4*)in;
    const float4* inB = (const float4*)tgt;
    const int P4    = PLANE / 4;                 // 65536
    const int base4 = n * 3 * P4 + tx;
    const int h0m7  = h0 - 7;
    const unsigned vspan = (unsigned)(sh + 13);  // rows h0-7 .. h0+sh+6

    float vs0 = 0.f, vs1 = 0.f, vs2 = 0.f;
    float ac0 = 0.f, ac1 = 0.f, ac2 = 0.f;

    #pragma unroll 6
    for (int it = 0; it <= ITERS; ++it) {        // 12 iterations
        const int p = it & 1;                    // sd buffer parity
        const int planebase = (p * 12 + ty * 3); // sd/s4 plane index base

        // ---- phase A: group it (skip on epilogue iteration) ----
        if (it < ITERS) {
            const int grel = 4 * it - 8;
            const int hr   = h0 + grel + ty;
            const bool valid = ((unsigned)(hr - h0m7) <= vspan) &&
                               ((unsigned)hr < (unsigned)H_);
            const int hrc = min(max(hr, 0), H_ - 1);
            const int rb  = base4 + hrc * (W_ / 4);
            float4 ra = inA[rb], ga = inA[rb + P4], ba = inA[rb + 2 * P4];
            float4 rc = inB[rb], gc = inB[rb + P4], bc = inB[rb + 2 * P4];

            u64 d0a = 0, d1a = 0, d2a = 0, d0b = 0, d1b = 0, d2b = 0;
            if (valid) {
                u64 lA, uA, vA, lB, uB, vB;
                luv2(pk(ra.x, ra.y), pk(ga.x, ga.y), pk(ba.x, ba.y), lA, uA, vA);
                luv2(pk(rc.x, rc.y), pk(gc.x, gc.y), pk(bc.x, bc.y), lB, uB, vB);
                d0a = fma2(lB, NEG1, lA);
                d1a = fma2(uB, NEG1, uA);
                d2a = fma2(vB, NEG1, vA);
                luv2(pk(ra.z, ra.w), pk(ga.z, ga.w), pk(ba.z, ba.w), lA, uA, vA);
                luv2(pk(rc.z, rc.w), pk(gc.z, gc.w), pk(bc.z, bc.w), lB, uB, vB);
                d0b = fma2(lB, NEG1, lA);
                d1b = fma2(uB, NEG1, uA);
                d2b = fma2(vB, NEG1, vA);
            }
            #pragma unroll
            for (int ch = 0; ch < 3; ch++) {
                u64 da = (ch == 0) ? d0a : (ch == 1) ? d1a : d2a;
                u64 db = (ch == 0) ? d0b : (ch == 1) ? d1b : d2b;
                float f0, f1, f2, f3;
                upk(f0, f1, da); upk(f2, f3, db);
                *(uint2*)&sdh[(planebase + ch) * SD_STRIDE + 8 + 4 * tx] =
                    make_uint2(pack2h(f0, f1), pack2h(f2, f3));
                s4f[(planebase + ch) * S4_STRIDE + 2 + tx] = (f0 + f1) + (f2 + f3);
            }
        }
        __syncthreads();   // the ONLY barrier per group

        // ---- phase B: 15-tap hbox for group it -> ring ----
        if (it < ITERS) {
            float hbL[4], hbU[4], hbV[4];
            #pragma unroll
            for (int ch = 0; ch < 3; ch++) {
                const __half* sdc = sdh + (planebase + ch) * SD_STRIDE;
                const float*  s4c = s4f + (planebase + ch) * S4_STRIDE;
                float s0 = s4c[tx] + s4c[tx + 1] + s4c[tx + 2] + s4c[tx + 3];
                uint2 Lh = *(const uint2*)&sdc[4 * tx];       // d[4tx-8..4tx-5]
                uint2 Rh = *(const uint2*)&sdc[16 + 4 * tx];  // d[4tx+8..4tx+11]
                float2 l01 = __half22float2(*(__half2*)&Lh.x);
                float2 l23 = __half22float2(*(__half2*)&Lh.y);
                float2 r01 = __half22float2(*(__half2*)&Rh.x);
                float2 r23 = __half22float2(*(__half2*)&Rh.y);
                float* hb = (ch == 0) ? hbL : (ch == 1) ? hbU : hbV;
                hb[0] = s0 - l01.x;
                hb[1] = hb[0] + r01.x - l01.y;
                hb[2] = hb[1] + r01.y - l23.x;
                hb[3] = hb[2] + r23.x - l23.y;
            }
            const int slot_b = (4 * it + 16 + ty) % 24;   // row 4it-8+ty
            uint4* wlu = (uint4*)(ring_lu + slot_b * W_ + 4 * tx);
            *wlu = make_uint4(pack2h(hbL[0], hbU[0]), pack2h(hbL[1], hbU[1]),
                              pack2h(hbL[2], hbU[2]), pack2h(hbL[3], hbU[3]));
            *(uint2*)(ring_vh + slot_b * W_ + 4 * tx) =
                make_uint2(pack2h(hbV[0], hbV[1]), pack2h(hbV[2], hbV[3]));
        }

        // ---- phase C: vertical running sums for group it-1 (deferred) ----
        if (it >= 1) {
            #pragma unroll
            for (int j = 0; j < 4; j++) {
                const int r  = 4 * it - 12 + j;          // row rel. to h0
                const int sn = (4 * it + 12 + j) % 24;   // slot of row r
                const int so = (4 * it + 21 + j) % 24;   // slot of row r-15
                unsigned lun = ring_lu[sn * W_ + t];
                unsigned luo = ring_lu[so * W_ + t];
                __half   vn  = ring_vh[sn * W_ + t];
                __half   vo  = ring_vh[so * W_ + t];
                float2 fn = __half22float2(*(__half2*)&lun);
                float2 fo = __half22float2(*(__half2*)&luo);
                vs0 += fn.x - fo.x;
                vs1 += fn.y - fo.y;
                vs2 += h2f(vn) - h2f(vo);
                if ((unsigned)(r - 7) < (unsigned)sh) {  // output row r-7
                    ac0 = fmaf(vs0, vs0, ac0);
                    ac1 = fmaf(vs1, vs1, ac1);
                    ac2 = fmaf(vs2, vs2, ac2);
                }
            }
        }
    }

    // ---- block reduction ----
    #pragma unroll
    for (int o = 16; o > 0; o >>= 1) {
        ac0 += __shfl_down_sync(0xffffffffu, ac0, o);
        ac1 += __shfl_down_sync(0xffffffffu, ac1, o);
        ac2 += __shfl_down_sync(0xffffffffu, ac2, o);
    }
    __syncthreads();
    float* red = s4f;                              // reuse smem
    int wid = t >> 5, lane = t & 31;
    if (lane == 0) { red[wid] = ac0; red[16 + wid] = ac1; red[32 + wid] = ac2; }
    __syncthreads();
    if (t < 3) {
        float sm = 0.f;
        #pragma unroll
        for (int i = 0; i < 16; i++) sm += red[t * 16 + i];
        atomicAdd(&g_accum[t], (double)sm);
    }
    __threadfence();
    __syncthreads();

    // Last block finalizes and resets global state (graph-replay safe).
    __shared__ int is_last;
    if (t == 0) is_last = (atomicAdd(&g_done, 1) == NBLK - 1);
    __syncthreads();
    if (is_last && t == 0) {
        double total = g_accum[0] + g_accum[1] + g_accum[2];
        out[0] = (float)(total / (double)((size_t)N_ * PLANE));
        g_accum[0] = 0.0; g_accum[1] = 0.0; g_accum[2] = 0.0;
        g_done = 0;
    }
}

extern "C" void kernel_launch(void* const* d_in, const int* in_sizes, int n_in,
                              void* d_out, int out_size) {
    const float* in  = (const float*)d_in[0];
    const float* tgt = (const float*)d_in[1];
    float* out = (float*)d_out;

    cudaFuncSetAttribute(fused_kernel,
                         cudaFuncAttributeMaxDynamicSharedMemorySize, SMEM_BYTES);
    fused_kernel<<<NBLK, TPB, SMEM_BYTES>>>(in, tgt, out);
}